// round 5
// baseline (speedup 1.0000x reference)
#include <cuda_runtime.h>
#include <cstdint>

#define N_NODES 1024
#define F_IN    32
#define HID     64
#define OUTF    32

typedef unsigned long long u64;

// Scratch
__device__ float  g_A [N_NODES * HID];            // A[i][h]
__device__ float2 g_Bt[(HID / 2) * N_NODES];      // Bt[hp][i] = (B[i][2hp], B[i][2hp+1])

// ---------------------------------------------------------------------------
// Prep: A[i][h] = Emb[i]·W1[h][:F];  B[i][h] = Emb[i]·W1[h][F:]
// ---------------------------------------------------------------------------
__global__ void prep_kernel(const float* __restrict__ Emb,
                            const float* __restrict__ W1) {
    __shared__ float sW1[HID * 65];
    __shared__ float sE[F_IN];
    const int i = blockIdx.x;
    const int h = threadIdx.x;

    for (int idx = h; idx < HID * 2 * F_IN; idx += 64) {
        int r = idx >> 6, c = idx & 63;
        sW1[r * 65 + c] = W1[idx];
    }
    if (h < F_IN) sE[h] = Emb[i * F_IN + h];
    __syncthreads();

    float a = 0.f, b = 0.f;
#pragma unroll
    for (int f = 0; f < F_IN; f++) {
        float e = sE[f];
        a = fmaf(e, sW1[h * 65 + f], a);
        b = fmaf(e, sW1[h * 65 + F_IN + f], b);
    }
    g_A[i * HID + h] = a;
    ((float*)g_Bt)[(h >> 1) * (2 * N_NODES) + i * 2 + (h & 1)] = b;
}

// swish(x) = x*sigmoid(x) = 0.5x + 0.5x*tanh(x/2): 3 instrs, 1 MUFU.
__device__ __forceinline__ float swishf(float x) {
    float hx = 0.5f * x;
    float t;
    asm("tanh.approx.f32 %0, %1;" : "=f"(t) : "f"(hx));
    return fmaf(hx, t, hx);
}
__device__ __forceinline__ u64 pack2(float lo, float hi) {
    u64 r; asm("mov.b64 %0, {%1,%2};" : "=l"(r) : "f"(lo), "f"(hi)); return r;
}
__device__ __forceinline__ void unpack2(u64 v, float& lo, float& hi) {
    asm("mov.b64 {%0,%1}, %2;" : "=f"(lo), "=f"(hi) : "l"(v));
}
__device__ __forceinline__ void fma2(u64& acc, u64 a, u64 b) {
    asm("fma.rn.f32x2 %0, %1, %2, %0;" : "+l"(acc) : "l"(a), "l"(b));
}

// ---------------------------------------------------------------------------
// Main: grid (N/64, N/8), block 256 = 8 warps. Warp w owns row i = i0+w.
// Lane owns TWO pairs: (i, j0+lane) and (i, j0+32+lane); all 32 outputs per
// pair live in 16 packed f32x2 registers (pre-seeded with b2). h1 lives only
// in registers. Epilogue: swish + direct STG.128 (each lane owns a full
// contiguous 128B output row per pair — no transpose needed).
// ---------------------------------------------------------------------------
__global__ __launch_bounds__(256) void phi_e_kernel(
    const float* __restrict__ Edges,
    const float* __restrict__ Coords,
    const float* __restrict__ b1,
    const float* __restrict__ W2,
    const float* __restrict__ b2,
    float* __restrict__ out)
{
    __shared__ float2 sB2[HID / 2][64];                    // Bt tile for 64 j's
    __shared__ __align__(16) float sW2T[HID * 36];         // W2^T, rows padded to 36
    __shared__ float4 sC[8][HID / 2];                      // (A[2hp], b1[2hp], A[2hp+1], b1[2hp+1])
    __shared__ __align__(8) float sb2s[OUTF];

    const int tid  = threadIdx.x;
    const int warp = tid >> 5;
    const int lane = tid & 31;
    const int i0 = blockIdx.y * 8;
    const int j0 = blockIdx.x * 64;
    const int i  = i0 + warp;

    for (int e = tid; e < (HID / 2) * 64; e += 256) {
        int hp = e >> 6, jj = e & 63;
        sB2[hp][jj] = g_Bt[hp * N_NODES + j0 + jj];
    }
    for (int idx = tid; idx < OUTF * HID; idx += 256) {
        int o = idx >> 6, h = idx & 63;
        sW2T[h * 36 + o] = W2[idx];
    }
    {
        float2 a2 = ((const float2*)g_A)[i * (HID / 2) + lane];
        float2 bb = ((const float2*)b1)[lane];
        sC[warp][lane] = make_float4(a2.x, bb.x, a2.y, bb.y);
    }
    if (tid < OUTF) sb2s[tid] = b2[tid];

    float wA, wB;
    {
        float cx = Coords[i * 3 + 0], cy = Coords[i * 3 + 1], cz = Coords[i * 3 + 2];
        int jA = j0 + lane, jB = j0 + 32 + lane;
        float dxA = cx - Coords[jA * 3 + 0], dyA = cy - Coords[jA * 3 + 1], dzA = cz - Coords[jA * 3 + 2];
        float dxB = cx - Coords[jB * 3 + 0], dyB = cy - Coords[jB * 3 + 1], dzB = cz - Coords[jB * 3 + 2];
        float sqA = fmaf(dxA, dxA, fmaf(dyA, dyA, dzA * dzA));
        float sqB = fmaf(dxB, dxB, fmaf(dyB, dyB, dzB * dzB));
        float dA = sqA > 0.f ? __fsqrt_rn(sqA) : 0.f;
        float dB = sqB > 0.f ? __fsqrt_rn(sqB) : 0.f;
        wA = Edges[i * N_NODES + jA] * dA;
        wB = Edges[i * N_NODES + jB] * dB;
    }
    __syncthreads();

    // Accumulators pre-seeded with b2 (saves epilogue adds).
    u64 accA[16], accB[16];
#pragma unroll
    for (int p = 0; p < 16; p++) {
        float2 bb = ((const float2*)sb2s)[p];   // broadcast LDS.64
        accA[p] = pack2(bb.x, bb.y);
        accB[p] = accA[p];
    }

#pragma unroll 4
    for (int hp = 0; hp < HID / 2; hp++) {
        float4 c  = sC[warp][hp];                  // broadcast LDS.128
        float2 bA = sB2[hp][lane];                 // LDS.64
        float2 bB = sB2[hp][32 + lane];

        float hA0 = swishf(fmaf(wA, c.x + bA.x, c.y));
        float hA1 = swishf(fmaf(wA, c.z + bA.y, c.w));
        float hB0 = swishf(fmaf(wB, c.x + bB.x, c.y));
        float hB1 = swishf(fmaf(wB, c.z + bB.y, c.w));
        u64 pA0 = pack2(hA0, hA0), pA1 = pack2(hA1, hA1);
        u64 pB0 = pack2(hB0, hB0), pB1 = pack2(hB1, hB1);

        const ulonglong2* r0 = (const ulonglong2*)(sW2T + (2 * hp)     * 36);
        const ulonglong2* r1 = (const ulonglong2*)(sW2T + (2 * hp + 1) * 36);
#pragma unroll
        for (int q = 0; q < 8; q++) {
            ulonglong2 w0 = r0[q];                 // broadcast LDS.128
            ulonglong2 w1 = r1[q];
            fma2(accA[2 * q],     pA0, w0.x);
            fma2(accA[2 * q + 1], pA0, w0.y);
            fma2(accA[2 * q],     pA1, w1.x);
            fma2(accA[2 * q + 1], pA1, w1.y);
            fma2(accB[2 * q],     pB0, w0.x);
            fma2(accB[2 * q + 1], pB0, w0.y);
            fma2(accB[2 * q],     pB1, w1.x);
            fma2(accB[2 * q + 1], pB1, w1.y);
        }
    }

    // ---- epilogue: swish + direct STG.128 (lane owns contiguous 128B row) ----
#pragma unroll
    for (int s = 0; s < 2; s++) {
        u64* acc = s ? accB : accA;
        const int j = j0 + (s ? 32 : 0) + lane;
        float4* dst = (float4*)(out + ((size_t)i * N_NODES + j) * OUTF);

        float vals[32];
#pragma unroll
        for (int p = 0; p < 16; p++) unpack2(acc[p], vals[2 * p], vals[2 * p + 1]);
#pragma unroll
        for (int o = 0; o < OUTF; o++) vals[o] = swishf(vals[o]);

#pragma unroll
        for (int q = 0; q < 8; q++) {
            float4 v = make_float4(vals[4 * q], vals[4 * q + 1],
                                   vals[4 * q + 2], vals[4 * q + 3]);
            __stcs(dst + q, v);                    // streaming store, full-line coverage
        }
    }
}

// ---------------------------------------------------------------------------
extern "C" void kernel_launch(void* const* d_in, const int* in_sizes, int n_in,
                              void* d_out, int out_size) {
    const float* Edges  = (const float*)d_in[0];
    const float* Coords = (const float*)d_in[1];
    const float* Emb    = (const float*)d_in[2];
    const float* W1     = (const float*)d_in[3];
    const float* b1     = (const float*)d_in[4];
    const float* W2     = (const float*)d_in[5];
    const float* b2     = (const float*)d_in[6];
    float* out = (float*)d_out;

    prep_kernel<<<N_NODES, 64>>>(Emb, W1);

    dim3 grid(N_NODES / 64, N_NODES / 8);
    phi_e_kernel<<<grid, 256>>>(Edges, Coords, b1, W2, b2, out);
}

// round 6
// speedup vs baseline: 1.4670x; 1.4670x over previous
#include <cuda_runtime.h>
#include <cstdint>

#define N_NODES 1024
#define F_IN    32
#define HID     64
#define OUTF    32

typedef unsigned long long u64;

// Scratch
__device__ float  g_A  [N_NODES * HID];
__device__ float2 g_Bt [(HID / 2) * N_NODES];   // Bt[hp][i]
__device__ float  g_W2T[HID * OUTF];            // W2^T [h][o]

// Constant copies (uniform operands -> constant port, off the L1 crossbar)
__constant__ float c_W2T[HID * OUTF];
__constant__ float c_b2 [OUTF];

// ---------------------------------------------------------------------------
__global__ void prep_kernel(const float* __restrict__ Emb,
                            const float* __restrict__ W1) {
    __shared__ float sW1[HID * 65];
    __shared__ float sE[F_IN];
    const int i = blockIdx.x;
    const int h = threadIdx.x;

    for (int idx = h; idx < HID * 2 * F_IN; idx += 64) {
        int r = idx >> 6, c = idx & 63;
        sW1[r * 65 + c] = W1[idx];
    }
    if (h < F_IN) sE[h] = Emb[i * F_IN + h];
    __syncthreads();

    float a = 0.f, b = 0.f;
#pragma unroll
    for (int f = 0; f < F_IN; f++) {
        float e = sE[f];
        a = fmaf(e, sW1[h * 65 + f], a);
        b = fmaf(e, sW1[h * 65 + F_IN + f], b);
    }
    g_A[i * HID + h] = a;
    ((float*)g_Bt)[(h >> 1) * (2 * N_NODES) + i * 2 + (h & 1)] = b;
}

__global__ void transpose_w2_kernel(const float* __restrict__ W2) {
    int idx = threadIdx.x + blockIdx.x * blockDim.x;     // 2048 threads
    int o = idx >> 6, h = idx & 63;
    g_W2T[h * OUTF + o] = W2[o * HID + h];
}

// swish(x) = 0.5x + 0.5x*tanh(x/2): 3 instrs, 1 MUFU.
__device__ __forceinline__ float swishf(float x) {
    float hx = 0.5f * x;
    float t;
    asm("tanh.approx.f32 %0, %1;" : "=f"(t) : "f"(hx));
    return fmaf(hx, t, hx);
}
__device__ __forceinline__ u64 pack2(float lo, float hi) {
    u64 r; asm("mov.b64 %0, {%1,%2};" : "=l"(r) : "f"(lo), "f"(hi)); return r;
}
__device__ __forceinline__ void unpack2(u64 v, float& lo, float& hi) {
    asm("mov.b64 {%0,%1}, %2;" : "=f"(lo), "=f"(hi) : "l"(v));
}
__device__ __forceinline__ void fma2(u64& acc, u64 a, u64 b) {
    asm("fma.rn.f32x2 %0, %1, %2, %0;" : "+l"(acc) : "l"(a), "l"(b));
}

// ---------------------------------------------------------------------------
// grid (N/64, N/8), block 256 = 8 warps. Lane owns pairs (i, j0+lane) and
// (i, j0+32+lane); 16 packed-f32x2 accumulators per pair, preseeded with b2.
// W2^T streamed from __constant__ (constant port). Coalesced store via the
// proven smem-transpose epilogue.
// ---------------------------------------------------------------------------
__global__ __launch_bounds__(256, 2) void phi_e_kernel(
    const float* __restrict__ Edges,
    const float* __restrict__ Coords,
    const float* __restrict__ b1,
    float* __restrict__ out)
{
    __shared__ float2 sB2[HID / 2][64];                // Bt tile for 64 j's
    __shared__ float4 sC[8][HID / 2];                  // (A[2hp], b1[2hp], A[2hp+1], b1[2hp+1])
    __shared__ float  sOut[8][32][17];                 // epilogue staging

    const int tid  = threadIdx.x;
    const int warp = tid >> 5;
    const int lane = tid & 31;
    const int i0 = blockIdx.y * 8;
    const int j0 = blockIdx.x * 64;
    const int i  = i0 + warp;

    for (int e = tid; e < (HID / 2) * 64; e += 256) {
        int hp = e >> 6, jj = e & 63;
        sB2[hp][jj] = g_Bt[hp * N_NODES + j0 + jj];
    }
    {
        float2 a2 = ((const float2*)g_A)[i * (HID / 2) + lane];
        float2 bb = ((const float2*)b1)[lane];
        sC[warp][lane] = make_float4(a2.x, bb.x, a2.y, bb.y);
    }

    float wA, wB;
    {
        float cx = Coords[i * 3 + 0], cy = Coords[i * 3 + 1], cz = Coords[i * 3 + 2];
        int jA = j0 + lane, jB = j0 + 32 + lane;
        float dxA = cx - Coords[jA * 3 + 0], dyA = cy - Coords[jA * 3 + 1], dzA = cz - Coords[jA * 3 + 2];
        float dxB = cx - Coords[jB * 3 + 0], dyB = cy - Coords[jB * 3 + 1], dzB = cz - Coords[jB * 3 + 2];
        float sqA = fmaf(dxA, dxA, fmaf(dyA, dyA, dzA * dzA));
        float sqB = fmaf(dxB, dxB, fmaf(dyB, dyB, dzB * dzB));
        float dA = sqA > 0.f ? __fsqrt_rn(sqA) : 0.f;
        float dB = sqB > 0.f ? __fsqrt_rn(sqB) : 0.f;
        wA = Edges[i * N_NODES + jA] * dA;
        wB = Edges[i * N_NODES + jB] * dB;
    }
    __syncthreads();

    // Accumulators preseeded with b2 (from constant).
    u64 accA[16], accB[16];
#pragma unroll
    for (int p = 0; p < 16; p++) {
        accA[p] = pack2(c_b2[2 * p], c_b2[2 * p + 1]);
        accB[p] = accA[p];
    }

#pragma unroll 4
    for (int hp = 0; hp < HID / 2; hp++) {
        float4 c  = sC[warp][hp];                      // broadcast LDS.128
        float2 bA = sB2[hp][lane];                     // LDS.64
        float2 bB = sB2[hp][32 + lane];

        float hA0 = swishf(fmaf(wA, c.x + bA.x, c.y));
        float hA1 = swishf(fmaf(wA, c.z + bA.y, c.w));
        float hB0 = swishf(fmaf(wB, c.x + bB.x, c.y));
        float hB1 = swishf(fmaf(wB, c.z + bB.y, c.w));
        u64 pA0 = pack2(hA0, hA0), pA1 = pack2(hA1, hA1);
        u64 pB0 = pack2(hB0, hB0), pB1 = pack2(hB1, hB1);

        const ulonglong2* r0 = (const ulonglong2*)(c_W2T + (2 * hp)     * OUTF);
        const ulonglong2* r1 = (const ulonglong2*)(c_W2T + (2 * hp + 1) * OUTF);
#pragma unroll
        for (int q = 0; q < 8; q++) {
            ulonglong2 w0 = r0[q];                     // LDC.128 (constant port)
            ulonglong2 w1 = r1[q];
            fma2(accA[2 * q],     pA0, w0.x);
            fma2(accA[2 * q + 1], pA0, w0.y);
            fma2(accA[2 * q],     pA1, w1.x);
            fma2(accA[2 * q + 1], pA1, w1.y);
            fma2(accB[2 * q],     pB0, w0.x);
            fma2(accB[2 * q + 1], pB0, w0.y);
            fma2(accB[2 * q],     pB1, w1.x);
            fma2(accB[2 * q + 1], pB1, w1.y);
        }
    }

    // ---- epilogue: swish + coalesced store via padded smem transpose ----
    const int t   = lane & 15;
    const int jj2 = lane >> 4;
#pragma unroll
    for (int s = 0; s < 2; s++) {
        u64* acc = s ? accB : accA;
        float* obase = out + ((size_t)i * N_NODES + j0 + (s ? 32 : 0)) * OUTF;

        float vals[32];
#pragma unroll
        for (int p = 0; p < 16; p++) unpack2(acc[p], vals[2 * p], vals[2 * p + 1]);
#pragma unroll
        for (int o = 0; o < OUTF; o++) vals[o] = swishf(vals[o]);

#pragma unroll
        for (int r = 0; r < 2; r++) {
#pragma unroll
            for (int k = 0; k < 16; k++) sOut[warp][lane][k] = vals[16 * r + k];
            __syncwarp();
#pragma unroll
            for (int c = 0; c < 16; c++) {
                int jj = 2 * c + jj2;
                obase[jj * OUTF + 16 * r + t] = sOut[warp][jj][t];
            }
            __syncwarp();
        }
    }
}

// ---------------------------------------------------------------------------
extern "C" void kernel_launch(void* const* d_in, const int* in_sizes, int n_in,
                              void* d_out, int out_size) {
    const float* Edges  = (const float*)d_in[0];
    const float* Coords = (const float*)d_in[1];
    const float* Emb    = (const float*)d_in[2];
    const float* W1     = (const float*)d_in[3];
    const float* b1     = (const float*)d_in[4];
    const float* W2     = (const float*)d_in[5];
    const float* b2     = (const float*)d_in[6];
    float* out = (float*)d_out;

    prep_kernel<<<N_NODES, 64>>>(Emb, W1);
    transpose_w2_kernel<<<8, 256>>>(W2);

    // D2D copies into constant memory (graph-capturable memcpy nodes).
    void* w2t_dev = nullptr;
    cudaGetSymbolAddress(&w2t_dev, g_W2T);
    cudaMemcpyToSymbolAsync(c_W2T, w2t_dev, HID * OUTF * sizeof(float), 0,
                            cudaMemcpyDeviceToDevice);
    cudaMemcpyToSymbolAsync(c_b2, b2, OUTF * sizeof(float), 0,
                            cudaMemcpyDeviceToDevice);

    dim3 grid(N_NODES / 64, N_NODES / 8);
    phi_e_kernel<<<grid, 256>>>(Edges, Coords, b1, out);
}

// round 7
// speedup vs baseline: 1.4851x; 1.0123x over previous
#include <cuda_runtime.h>
#include <cstdint>

#define N_NODES 1024
#define F_IN    32
#define HID     64
#define OUTF    32

typedef unsigned long long u64;

// Scratch
__device__ float  g_A  [N_NODES * HID];
__device__ float2 g_Bt [(HID / 2) * N_NODES];   // Bt[hp][i]
__device__ float  g_W2T[HID * OUTF];            // W2^T [h][o]

// Constant copies (uniform operands -> constant port, off the L1 crossbar)
__constant__ float c_W2T[HID * OUTF];
__constant__ float c_b2 [OUTF];

// ---------------------------------------------------------------------------
// Prep: 64 blocks x 256 threads, 16 nodes/block. W1 staged once per block.
// ---------------------------------------------------------------------------
__global__ __launch_bounds__(256) void prep_kernel(const float* __restrict__ Emb,
                                                   const float* __restrict__ W1) {
    __shared__ float sW1[HID * 65];
    __shared__ float sE[16 * F_IN];
    const int tid = threadIdx.x;
    const int i0  = blockIdx.x * 16;

    for (int idx = tid; idx < HID * 2 * F_IN; idx += 256) {
        int r = idx >> 6, c = idx & 63;
        sW1[r * 65 + c] = W1[idx];
    }
    for (int idx = tid; idx < 16 * F_IN; idx += 256)
        sE[idx] = Emb[i0 * F_IN + idx];
    __syncthreads();

    const int h  = tid & 63;
    const int n0 = tid >> 6;            // 0..3
#pragma unroll
    for (int k = 0; k < 4; k++) {
        const int n = n0 * 4 + k;
        const float* e = &sE[n * F_IN];
        float a = 0.f, b = 0.f;
#pragma unroll
        for (int f = 0; f < F_IN; f++) {
            float ev = e[f];
            a = fmaf(ev, sW1[h * 65 + f], a);
            b = fmaf(ev, sW1[h * 65 + F_IN + f], b);
        }
        const int i = i0 + n;
        g_A[i * HID + h] = a;
        ((float*)g_Bt)[(h >> 1) * (2 * N_NODES) + i * 2 + (h & 1)] = b;
    }
}

__global__ void transpose_w2_kernel(const float* __restrict__ W2) {
    int idx = threadIdx.x + blockIdx.x * blockDim.x;     // 2048 threads
    int o = idx >> 6, h = idx & 63;
    g_W2T[h * OUTF + o] = W2[o * HID + h];
}

// ---------------------------------------------------------------------------
__device__ __forceinline__ u64 pack2(float lo, float hi) {
    u64 r; asm("mov.b64 %0, {%1,%2};" : "=l"(r) : "f"(lo), "f"(hi)); return r;
}
__device__ __forceinline__ void unpack2(u64 v, float& lo, float& hi) {
    asm("mov.b64 {%0,%1}, %2;" : "=f"(lo), "=f"(hi) : "l"(v));
}
__device__ __forceinline__ void fma2(u64& acc, u64 a, u64 b) {
    asm("fma.rn.f32x2 %0, %1, %2, %0;" : "+l"(acc) : "l"(a), "l"(b));
}
__device__ __forceinline__ u64 fma2r(u64 a, u64 b, u64 c) {
    u64 d; asm("fma.rn.f32x2 %0, %1, %2, %3;" : "=l"(d) : "l"(a), "l"(b), "l"(c)); return d;
}
__device__ __forceinline__ u64 add2r(u64 a, u64 b) {
    u64 d; asm("add.rn.f32x2 %0, %1, %2;" : "=l"(d) : "l"(a), "l"(b)); return d;
}
__device__ __forceinline__ u64 mul2r(u64 a, u64 b) {
    u64 d; asm("mul.rn.f32x2 %0, %1, %2;" : "=l"(d) : "l"(a), "l"(b)); return d;
}
__device__ __forceinline__ float tanhf_a(float x) {
    float t; asm("tanh.approx.f32 %0, %1;" : "=f"(t) : "f"(x)); return t;
}

// ---------------------------------------------------------------------------
// Main: grid (N/64, N/8), block 256 = 8 warps. Lane owns pairs (i, j0+lane)
// and (i, j0+32+lane). Phase A fully packed f32x2; W2^T from constant port;
// accumulators preseeded with b2; smem-transpose epilogue for coalesced STG.
// ---------------------------------------------------------------------------
__global__ __launch_bounds__(256, 2) void phi_e_kernel(
    const float* __restrict__ Edges,
    const float* __restrict__ Coords,
    const float* __restrict__ b1,
    float* __restrict__ out)
{
    __shared__ u64  sB2u[HID / 2][64];                 // packed Bt tile
    __shared__ u64  sCA[8][HID / 2];                   // packed A pairs per warp-row
    __shared__ u64  sb1p[HID / 2];                     // packed b1 pairs
    __shared__ float sOut[8][32][17];                  // epilogue staging

    const int tid  = threadIdx.x;
    const int warp = tid >> 5;
    const int lane = tid & 31;
    const int i0 = blockIdx.y * 8;
    const int j0 = blockIdx.x * 64;
    const int i  = i0 + warp;

    for (int e = tid; e < (HID / 2) * 64; e += 256) {
        int hp = e >> 6, jj = e & 63;
        float2 v = g_Bt[hp * N_NODES + j0 + jj];
        sB2u[hp][jj] = pack2(v.x, v.y);
    }
    {
        float2 a2 = ((const float2*)g_A)[i * (HID / 2) + lane];
        sCA[warp][lane] = pack2(a2.x, a2.y);
    }
    if (tid < HID / 2) {
        float2 bb = ((const float2*)b1)[tid];
        sb1p[tid] = pack2(bb.x, bb.y);
    }

    float wA, wB;
    {
        float cx = Coords[i * 3 + 0], cy = Coords[i * 3 + 1], cz = Coords[i * 3 + 2];
        int jA = j0 + lane, jB = j0 + 32 + lane;
        float dxA = cx - Coords[jA * 3 + 0], dyA = cy - Coords[jA * 3 + 1], dzA = cz - Coords[jA * 3 + 2];
        float dxB = cx - Coords[jB * 3 + 0], dyB = cy - Coords[jB * 3 + 1], dzB = cz - Coords[jB * 3 + 2];
        float sqA = fmaf(dxA, dxA, fmaf(dyA, dyA, dzA * dzA));
        float sqB = fmaf(dxB, dxB, fmaf(dyB, dyB, dzB * dzB));
        float dA = sqA > 0.f ? __fsqrt_rn(sqA) : 0.f;
        float dB = sqB > 0.f ? __fsqrt_rn(sqB) : 0.f;
        wA = Edges[i * N_NODES + jA] * dA;
        wB = Edges[i * N_NODES + jB] * dB;
    }
    __syncthreads();

    const u64 wpA  = pack2(wA, wA);
    const u64 wpB  = pack2(wB, wB);
    const u64 halfp = pack2(0.5f, 0.5f);

    // Accumulators preseeded with b2 (from constant).
    u64 accA[16], accB[16];
#pragma unroll
    for (int p = 0; p < 16; p++) {
        accA[p] = pack2(c_b2[2 * p], c_b2[2 * p + 1]);
        accB[p] = accA[p];
    }

#pragma unroll 4
    for (int hp = 0; hp < HID / 2; hp++) {
        u64 cA  = sCA[warp][hp];                       // broadcast LDS.64
        u64 b1v = sb1p[hp];                            // broadcast LDS.64
        u64 bA  = sB2u[hp][lane];                      // LDS.64
        u64 bB  = sB2u[hp][32 + lane];

        // pre1 = w*(A+B) + b1, packed over the h-pair
        u64 preA = fma2r(wpA, add2r(cA, bA), b1v);
        u64 preB = fma2r(wpB, add2r(cA, bB), b1v);

        // swish(x) = hx + hx*tanh(hx), hx = x/2 (packed mul, scalar MUFU)
        u64 hxA = mul2r(preA, halfp);
        u64 hxB = mul2r(preB, halfp);
        float hA0x, hA1x, hB0x, hB1x;
        unpack2(hxA, hA0x, hA1x);
        unpack2(hxB, hB0x, hB1x);
        float hA0 = fmaf(hA0x, tanhf_a(hA0x), hA0x);
        float hA1 = fmaf(hA1x, tanhf_a(hA1x), hA1x);
        float hB0 = fmaf(hB0x, tanhf_a(hB0x), hB0x);
        float hB1 = fmaf(hB1x, tanhf_a(hB1x), hB1x);

        u64 pA0 = pack2(hA0, hA0), pA1 = pack2(hA1, hA1);
        u64 pB0 = pack2(hB0, hB0), pB1 = pack2(hB1, hB1);

        const ulonglong2* r0 = (const ulonglong2*)(c_W2T + (2 * hp)     * OUTF);
        const ulonglong2* r1 = (const ulonglong2*)(c_W2T + (2 * hp + 1) * OUTF);
#pragma unroll
        for (int q = 0; q < 8; q++) {
            ulonglong2 w0 = r0[q];                     // constant port
            ulonglong2 w1 = r1[q];
            fma2(accA[2 * q],     pA0, w0.x);
            fma2(accA[2 * q + 1], pA0, w0.y);
            fma2(accA[2 * q],     pA1, w1.x);
            fma2(accA[2 * q + 1], pA1, w1.y);
            fma2(accB[2 * q],     pB0, w0.x);
            fma2(accB[2 * q + 1], pB0, w0.y);
            fma2(accB[2 * q],     pB1, w1.x);
            fma2(accB[2 * q + 1], pB1, w1.y);
        }
    }

    // ---- epilogue: swish + coalesced store via padded smem transpose ----
    const int t   = lane & 15;
    const int jj2 = lane >> 4;
#pragma unroll
    for (int s = 0; s < 2; s++) {
        u64* acc = s ? accB : accA;
        float* obase = out + ((size_t)i * N_NODES + j0 + (s ? 32 : 0)) * OUTF;

        float vals[32];
#pragma unroll
        for (int p = 0; p < 16; p++) {
            u64 hx2 = mul2r(acc[p], halfp);
            float h0, h1;
            unpack2(hx2, h0, h1);
            vals[2 * p]     = fmaf(h0, tanhf_a(h0), h0);
            vals[2 * p + 1] = fmaf(h1, tanhf_a(h1), h1);
        }

#pragma unroll
        for (int r = 0; r < 2; r++) {
#pragma unroll
            for (int k = 0; k < 16; k++) sOut[warp][lane][k] = vals[16 * r + k];
            __syncwarp();
#pragma unroll
            for (int c = 0; c < 16; c++) {
                int jj = 2 * c + jj2;
                obase[jj * OUTF + 16 * r + t] = sOut[warp][jj][t];
            }
            __syncwarp();
        }
    }
}

// ---------------------------------------------------------------------------
extern "C" void kernel_launch(void* const* d_in, const int* in_sizes, int n_in,
                              void* d_out, int out_size) {
    const float* Edges  = (const float*)d_in[0];
    const float* Coords = (const float*)d_in[1];
    const float* Emb    = (const float*)d_in[2];
    const float* W1     = (const float*)d_in[3];
    const float* b1     = (const float*)d_in[4];
    const float* W2     = (const float*)d_in[5];
    const float* b2     = (const float*)d_in[6];
    float* out = (float*)d_out;

    prep_kernel<<<64, 256>>>(Emb, W1);
    transpose_w2_kernel<<<8, 256>>>(W2);

    void* w2t_dev = nullptr;
    cudaGetSymbolAddress(&w2t_dev, g_W2T);
    cudaMemcpyToSymbolAsync(c_W2T, w2t_dev, HID * OUTF * sizeof(float), 0,
                            cudaMemcpyDeviceToDevice);
    cudaMemcpyToSymbolAsync(c_b2, b2, OUTF * sizeof(float), 0,
                            cudaMemcpyDeviceToDevice);

    dim3 grid(N_NODES / 64, N_NODES / 8);
    phi_e_kernel<<<grid, 256>>>(Edges, Coords, b1, out);
}